// round 16
// baseline (speedup 1.0000x reference)
#include <cuda_runtime.h>
#include <cuda_bf16.h>
#include <cuda_fp16.h>
#include <cstdint>

#define BB 32
#define NN 64
#define FF 128
#define KK 4
#define EE 4032

// ---------------- static device scratch (no allocations) ----------------
__device__ __align__(16) unsigned char g_w1r[KK * 2 * 256 * 272];
__device__ __align__(16) unsigned char g_w1s[KK * 2 * 256 * 272];
__device__ __align__(16) unsigned char g_w2img[KK * 256 * 528];
__device__ __align__(16) unsigned char g_wo1[256 * 784];
__device__ __align__(16) unsigned char g_wo2[256 * 528];
__device__ __align__(16) unsigned char g_wo3[128 * 528];
__device__ __align__(16) float    g_hb[KK * BB * NN * 256];
__device__ __align__(16) uint16_t g_simg[KK * BB * NN * 256];
__device__ float g_agg[2 * BB * NN * 256];   // two k-partials

// ---------------- helpers ----------------
__device__ __forceinline__ uint32_t smem_u32(const void* p) {
    uint32_t a;
    asm("{ .reg .u64 t; cvta.to.shared.u64 t, %1; cvt.u32.u64 %0, t; }" : "=r"(a) : "l"(p));
    return a;
}
__device__ __forceinline__ void split2(float2 v, uint32_t& hi, uint32_t& lo) {  // bf16
    __nv_bfloat162 h2 = __float22bfloat162_rn(v);
    float2 r = make_float2(v.x - __bfloat162float(h2.x), v.y - __bfloat162float(h2.y));
    __nv_bfloat162 l2 = __float22bfloat162_rn(r);
    hi = reinterpret_cast<uint32_t&>(h2);
    lo = reinterpret_cast<uint32_t&>(l2);
}
__device__ __forceinline__ uint32_t h2pack(float a, float b) {
    __half2 h = __float22half2_rn(make_float2(a, b));
    return reinterpret_cast<uint32_t&>(h);
}
__device__ __forceinline__ void ldm4(uint32_t addr, uint32_t r[4]) {
    asm volatile("ldmatrix.sync.aligned.m8n8.x4.shared.b16 {%0,%1,%2,%3}, [%4];"
                 : "=r"(r[0]), "=r"(r[1]), "=r"(r[2]), "=r"(r[3]) : "r"(addr));
}
__device__ __forceinline__ void mma_bf16(float* c, const uint32_t* a, uint32_t b0, uint32_t b1) {
    asm volatile(
        "mma.sync.aligned.m16n8k16.row.col.f32.bf16.bf16.f32 "
        "{%0,%1,%2,%3}, {%4,%5,%6,%7}, {%8,%9}, {%0,%1,%2,%3};"
        : "+f"(c[0]), "+f"(c[1]), "+f"(c[2]), "+f"(c[3])
        : "r"(a[0]), "r"(a[1]), "r"(a[2]), "r"(a[3]), "r"(b0), "r"(b1));
}
__device__ __forceinline__ void mma_f16(float* c, const uint32_t* a, uint32_t b0, uint32_t b1) {
    asm volatile(
        "mma.sync.aligned.m16n8k16.row.col.f32.f16.f16.f32 "
        "{%0,%1,%2,%3}, {%4,%5,%6,%7}, {%8,%9}, {%0,%1,%2,%3};"
        : "+f"(c[0]), "+f"(c[1]), "+f"(c[2]), "+f"(c[3])
        : "r"(a[0]), "r"(a[1]), "r"(a[2]), "r"(a[3]), "r"(b0), "r"(b1));
}
__device__ __forceinline__ void cpa16(uint32_t dst, const void* src) {
    asm volatile("cp.async.cg.shared.global [%0], [%1], 16;" :: "r"(dst), "l"(src));
}
#define CP_COMMIT() asm volatile("cp.async.commit_group;" ::: "memory")
#define CP_WAIT0()  asm volatile("cp.async.wait_group 0;" ::: "memory")

// =====================================================================
// prep_all_kernel: weight images only (704 blocks).
//  [0,128)    W1 recv -> g_w1r
//  [128,256)  W1 send -> g_w1s
//  [256,512)  W2      -> g_w2img
//  [512,608)  Wo1     -> g_wo1
//  [608,672)  Wo2     -> g_wo2
//  [672,704)  Wo3     -> g_wo3
// =====================================================================
__device__ __forceinline__ void prep_w_body(const float* Wk, int koff, int f0, int nn0,
                                            int kt, unsigned char* img, int rstride,
                                            float ts[32][33], int tid)
{
#pragma unroll
    for (int p = 0; p < 4; ++p) {
        int fr = (tid >> 5) + p * 8, nl = tid & 31;
        ts[fr][nl] = Wk[(size_t)(koff + f0 + fr) * 256 + nn0 + nl];
    }
    __syncthreads();
#pragma unroll
    for (int p = 0; p < 2; ++p) {
        int idx = tid + p * 256;
        int nr = idx >> 4, wp = idx & 15;
        uint32_t hi, lo;
        split2(make_float2(ts[2 * wp][nr], ts[2 * wp + 1][nr]), hi, lo);
        size_t rb = (size_t)(nn0 + nr) * rstride + (f0 + 2 * wp) * 2;
        *(uint32_t*)(img + (size_t)(kt * 2 + 0) * 256 * rstride + rb) = hi;
        *(uint32_t*)(img + (size_t)(kt * 2 + 1) * 256 * rstride + rb) = lo;
    }
}
__device__ __forceinline__ void prep_h_body(const float* W, int Ncols, int f0, int nn0,
                                            unsigned char* img, int rstride,
                                            float ts[32][33], int tid)
{
#pragma unroll
    for (int p = 0; p < 4; ++p) {
        int fr = (tid >> 5) + p * 8, nl = tid & 31;
        ts[fr][nl] = W[(size_t)(f0 + fr) * Ncols + nn0 + nl];
    }
    __syncthreads();
#pragma unroll
    for (int p = 0; p < 2; ++p) {
        int idx = tid + p * 256;
        int nr = idx >> 4, wp = idx & 15;
        *(uint32_t*)(img + (size_t)(nn0 + nr) * rstride + (f0 + 2 * wp) * 2) =
            h2pack(ts[2 * wp][nr], ts[2 * wp + 1][nr]);
    }
}

__global__ void __launch_bounds__(256)
prep_all_kernel(const float* __restrict__ W1, const float* __restrict__ W2,
                const float* __restrict__ Wo1, const float* __restrict__ Wo2,
                const float* __restrict__ Wo3,
                unsigned char* __restrict__ w1r, unsigned char* __restrict__ w1s,
                unsigned char* __restrict__ w2i,
                unsigned char* __restrict__ wo1i, unsigned char* __restrict__ wo2i,
                unsigned char* __restrict__ wo3i)
{
    __shared__ float ts[32][33];
    const int bid = blockIdx.x, tid = threadIdx.x;

    if (bid < 128) {
        int b2 = bid;
        prep_w_body(W1 + (size_t)(b2 >> 5) * 65536, 0, (b2 & 3) * 32,
                    ((b2 >> 2) & 7) * 32, b2 >> 5, w1r, 272, ts, tid);
    } else if (bid < 256) {
        int b2 = bid - 128;
        prep_w_body(W1 + (size_t)(b2 >> 5) * 65536, 128, (b2 & 3) * 32,
                    ((b2 >> 2) & 7) * 32, b2 >> 5, w1s, 272, ts, tid);
    } else if (bid < 512) {
        int b3 = bid - 256;
        int f0 = (b3 & 7) * 32, nn0 = ((b3 >> 3) & 7) * 32, kt = b3 >> 6;
        prep_h_body(W2 + (size_t)kt * 65536, 256, f0, nn0,
                    w2i + (size_t)kt * 256 * 528, 528, ts, tid);
    } else if (bid < 608) {
        int b4 = bid - 512;
        prep_h_body(Wo1, 256, (b4 % 12) * 32, (b4 / 12) * 32, wo1i, 784, ts, tid);
    } else if (bid < 672) {
        int b5 = bid - 608;
        prep_h_body(Wo2, 256, (b5 & 7) * 32, (b5 >> 3) * 32, wo2i, 528, ts, tid);
    } else {
        int b6 = bid - 672;
        prep_h_body(Wo3, 128, (b6 & 7) * 32, (b6 >> 3) * 32, wo3i, 528, ts, tid);
    }
}

// =====================================================================
// ns_kernel: converts X inline (no prep_x dependency).
// per (k,b,z): node GEMM [64x128]@[128x128] (3-split bf16).
// =====================================================================
#define NS_XHI 0
#define NS_XLO 17408
#define NS_W   34816      // doubles as fp32-X staging (32 KB <= 34816)
#define NS_B1  69632
#define NS_TOTAL 70656

__global__ void __launch_bounds__(256)
ns_kernel(const float* __restrict__ inputs,
          const unsigned char* __restrict__ w1r, const unsigned char* __restrict__ w1s,
          const float* __restrict__ b1, float* __restrict__ hb, uint16_t* __restrict__ simg)
{
    extern __shared__ char smem[];
    const uint32_t sb = smem_u32(smem);
    const int tid = threadIdx.x, lane = tid & 31, w = tid >> 5;
    const int k = blockIdx.x, b = blockIdx.y;
    const int half = blockIdx.z >> 1, s0 = (blockIdx.z & 1) * 2;

    // stage X fp32 into NS_W region, then convert to bf16 hi/lo images
    {
        const float* xb = inputs + (size_t)b * NN * FF;
        for (int t = tid; t < 2048; t += 256)
            cpa16(sb + NS_W + t * 16, (const unsigned char*)xb + t * 16);
        CP_COMMIT();
    }
    if (tid < 64) ((float4*)(smem + NS_B1))[tid] = ((const float4*)(b1 + k * 256))[tid];
    CP_WAIT0();
    __syncthreads();
    {
        const float* xs = (const float*)(smem + NS_W);
        for (int t = tid; t < 4096; t += 256) {
            int r = t >> 6, pc = t & 63;
            float2 v = *(const float2*)(xs + r * 128 + pc * 2);
            uint32_t hi, lo;
            split2(v, hi, lo);
            *(uint32_t*)(smem + NS_XHI + r * 272 + pc * 4) = hi;
            *(uint32_t*)(smem + NS_XLO + r * 272 + pc * 4) = lo;
        }
    }
    __syncthreads();

    const int g = lane >> 2, tg = lane & 3;
    const int arow = lane & 15;
    const uint32_t aoff = (uint32_t)((lane >> 4) << 4);
    const int brow = (lane & 7) + ((lane >> 4) << 3);
    const uint32_t boff = (uint32_t)((lane & 8) << 1);
    const int wm = w & 3, wn = w >> 2;
    const int m0 = wm * 16;
    const float* b1s = (const float*)(smem + NS_B1);
    const unsigned char* img = half ? w1s : w1r;
    float* outh = hb + ((size_t)k * BB + b) * 64 * 256;
    uint32_t* outs = (uint32_t*)simg + ((size_t)k * BB + b) * 64 * 128;

#pragma unroll 1
    for (int si = 0; si < 2; ++si) {
        int s = s0 + si;
        for (int t = tid; t < 2176; t += 256) {
            int im = t >= 1088;
            uint32_t off = (uint32_t)(t - im * 1088) * 16;
            cpa16(sb + NS_W + (im ? 17408 : 0) + off,
                  img + (size_t)((k * 2 + im) * 256 + s * 64) * 272 + off);
        }
        CP_COMMIT(); CP_WAIT0();
        __syncthreads();
        float c[4][4] = {};
#pragma unroll
        for (int sp = 0; sp < 3; ++sp) {
            uint32_t Ab = sb + (sp == 2 ? NS_XLO : NS_XHI) + (m0 + arow) * 272 + aoff;
            uint32_t Bb = sb + NS_W + (sp == 1 ? 17408u : 0u) + (wn * 32 + brow) * 272 + boff;
#pragma unroll
            for (int ks = 0; ks < 8; ++ks) {
                uint32_t a[4], b0[4], b1f[4];
                ldm4(Ab + ks * 32, a);
                ldm4(Bb + ks * 32, b0);
                ldm4(Bb + 16 * 272 + ks * 32, b1f);
                mma_bf16(c[0], a, b0[0], b0[1]);
                mma_bf16(c[1], a, b0[2], b0[3]);
                mma_bf16(c[2], a, b1f[0], b1f[1]);
                mma_bf16(c[3], a, b1f[2], b1f[3]);
            }
        }
        int r0 = m0 + g, r1 = r0 + 8;
        int cn = s * 64 + wn * 32;
        if (half == 0) {
#pragma unroll
            for (int t = 0; t < 4; ++t) {
                int col = cn + t * 8 + 2 * tg;
                outh[(size_t)r0 * 256 + col]     = c[t][0] + b1s[col];
                outh[(size_t)r0 * 256 + col + 1] = c[t][1] + b1s[col + 1];
                outh[(size_t)r1 * 256 + col]     = c[t][2] + b1s[col];
                outh[(size_t)r1 * 256 + col + 1] = c[t][3] + b1s[col + 1];
            }
        } else {
#pragma unroll
            for (int t = 0; t < 4; ++t) {
                int col = cn + t * 8 + 2 * tg;
                outs[(size_t)r0 * 128 + (col >> 1)] = h2pack(c[t][0], c[t][1]);
                outs[(size_t)r1 * 128 + (col >> 1)] = h2pack(c[t][2], c[t][3]);
            }
        }
        __syncthreads();
    }
}

// ---------------- SMEM map (bytes) for edge kernel ----------------
#define SE_S    0
#define SE_W2   33792
#define SE_HBS  101376
#define SE_B2S  103424
#define SE_RTS  104448
#define SE_AGG  106496
#define SE_TOTAL 114688

// =====================================================================
// Edge kernel (unchanged from R15 winner).
// =====================================================================
__global__ void __launch_bounds__(256, 2)
edge_kernel(const float* __restrict__ rel_type,
            const unsigned char* __restrict__ w2img,
            const uint16_t* __restrict__ simg,
            const float* __restrict__ hb,
            const float* __restrict__ b2,
            float* __restrict__ agg)
{
    extern __shared__ char smem[];
    const uint32_t sb = smem_u32(smem);
    const int tid = threadIdx.x;
    const int lane = tid & 31, w = tid >> 5;
    const int n0 = blockIdx.x * 2, b = blockIdx.y;
    const int kbase = blockIdx.z * 2;

    {
        const unsigned char* sk = (const unsigned char*)simg +
                                  ((size_t)kbase * BB + b) * 64 * 512;
        for (int t = tid; t < 2048; t += 256) {
            int row = t >> 5, ch = t & 31;
            cpa16(sb + SE_S + row * 528 + ch * 16, sk + (size_t)row * 512 + ch * 16);
        }
        for (int t = tid; t < 2112; t += 256)
            cpa16(sb + SE_W2 + t * 16, w2img + (size_t)(kbase * 256) * 528 + t * 16);
        CP_COMMIT();
    }

    if (tid < 128) {
        int node = n0 + (tid >> 6), le = tid & 63;
        float4 v = make_float4(0.f, 0.f, 0.f, 0.f);
        if (le < 63) v = *(const float4*)(rel_type + ((size_t)b * EE + node * 63 + le) * KK);
        *(float4*)(smem + SE_RTS + tid * 16) = v;
    }
    for (int i = tid; i < 2048; i += 256) ((float*)(smem + SE_AGG))[i] = 0.f;

    const int g = lane >> 2, tg = lane & 3;
    const int brow = (lane & 7) + ((lane >> 4) << 3);
    const uint32_t boff = (uint32_t)((lane & 8) << 1);
    const int m0 = w * 16;
    const int nodeg = n0 + (w >> 2);
    const float* rts = (const float*)(smem + SE_RTS);
    const float* b2s = (const float*)(smem + SE_B2S);
    float* aggS = (float*)(smem + SE_AGG);

    const int rw0 = m0 + g, rw1 = rw0 + 8;
    const int le0 = rw0 & 63, le1 = rw1 & 63;
    const float msk0 = (le0 != 63) ? 1.f : 0.f;
    const float msk1 = (le1 != 63) ? 1.f : 0.f;
    const int j0 = (le0 != 63) ? (le0 + (le0 >= nodeg)) : 0;
    const int j1 = (le1 != 63) ? (le1 + (le1 >= nodeg)) : 0;

    uint32_t Ha[64];

#pragma unroll 1
    for (int ki = 0; ki < 2; ++ki) {
        const int k = kbase + ki;
        {
            const float* hbk = hb + (((size_t)k * BB + b) * 64 + n0) * 256;
            if (tid < 128) *(float4*)(smem + SE_HBS + tid * 16) = ((const float4*)hbk)[tid];
            else if (tid < 192)
                ((float4*)(smem + SE_B2S))[tid - 128] = ((const float4*)(b2 + k * 256))[tid - 128];
        }
        if (ki == 0) CP_WAIT0();
        __syncthreads();

        {
            const __half* S0 = (const __half*)(smem + SE_S) + j0 * 264;
            const __half* S1 = (const __half*)(smem + SE_S) + j1 * 264;
            const float* hbs = (const float*)(smem + SE_HBS) + (w >> 2) * 256;
#pragma unroll
            for (int ks = 0; ks < 16; ++ks) {
                int c = ks * 16 + 2 * tg;
                float2 h0 = *(const float2*)(hbs + c);
                float2 h8 = *(const float2*)(hbs + c + 8);
                __half2 a0 = *(const __half2*)(S0 + c);
                __half2 a8 = *(const __half2*)(S0 + c + 8);
                __half2 bq0 = *(const __half2*)(S1 + c);
                __half2 bq8 = *(const __half2*)(S1 + c + 8);
                Ha[ks*4+0] = h2pack(msk0 * fmaxf(h0.x + __low2float(a0), 0.f),
                                    msk0 * fmaxf(h0.y + __high2float(a0), 0.f));
                Ha[ks*4+1] = h2pack(msk1 * fmaxf(h0.x + __low2float(bq0), 0.f),
                                    msk1 * fmaxf(h0.y + __high2float(bq0), 0.f));
                Ha[ks*4+2] = h2pack(msk0 * fmaxf(h8.x + __low2float(a8), 0.f),
                                    msk0 * fmaxf(h8.y + __high2float(a8), 0.f));
                Ha[ks*4+3] = h2pack(msk1 * fmaxf(h8.x + __low2float(bq8), 0.f),
                                    msk1 * fmaxf(h8.y + __high2float(bq8), 0.f));
            }
        }

        const float wr0 = rts[rw0 * 4 + k], wr1 = rts[rw1 * 4 + k];
#pragma unroll 1
        for (int s = 0; s < 4; ++s) {
            const int gs = ki * 4 + s;
            CP_WAIT0();
            __syncthreads();
            if (gs < 7) {
                const int nk = kbase + ((gs + 1) >> 2), nslab = (gs + 1) & 3;
                uint32_t wb = SE_W2 + (uint32_t)(((gs + 1) & 1) * 33792);
                for (int t = tid; t < 2112; t += 256)
                    cpa16(sb + wb + t * 16,
                          w2img + (size_t)(nk * 256 + nslab * 64) * 528 + t * 16);
                if (s == 2 && ki == 0) {
                    const unsigned char* sk = (const unsigned char*)simg +
                                              ((size_t)(k + 1) * BB + b) * 64 * 512;
                    for (int t = tid; t < 2048; t += 256) {
                        int row = t >> 5, ch = t & 31;
                        cpa16(sb + SE_S + row * 528 + ch * 16,
                              sk + (size_t)row * 512 + ch * 16);
                    }
                }
                CP_COMMIT();
            }
            const uint32_t wbase = sb + SE_W2 + (uint32_t)((s & 1) * 33792);
#pragma unroll
            for (int h = 0; h < 2; ++h) {
                const uint32_t wbs = wbase + (h * 32 + brow) * 528 + boff;
                float c[4][4] = {};
#pragma unroll
                for (int ks = 0; ks < 16; ++ks) {
                    uint32_t b0[4], b1f[4];
                    ldm4(wbs + ks * 32, b0);
                    ldm4(wbs + 16 * 528 + ks * 32, b1f);
                    const uint32_t* a = Ha + ks * 4;
                    mma_f16(c[0], a, b0[0], b0[1]);
                    mma_f16(c[1], a, b0[2], b0[3]);
                    mma_f16(c[2], a, b1f[0], b1f[1]);
                    mma_f16(c[3], a, b1f[2], b1f[3]);
                }
                float p0[4], p1[4];
#pragma unroll
                for (int t = 0; t < 4; ++t) {
                    int col = s * 64 + h * 32 + t * 8 + 2 * tg;
                    float bc0 = b2s[col], bc1 = b2s[col + 1];
                    p0[t] = wr0 * fmaxf(c[t][0] + bc0, 0.f) + wr1 * fmaxf(c[t][2] + bc0, 0.f);
                    p1[t] = wr0 * fmaxf(c[t][1] + bc1, 0.f) + wr1 * fmaxf(c[t][3] + bc1, 0.f);
                }
#pragma unroll
                for (int off = 4; off <= 16; off <<= 1)
#pragma unroll
                    for (int t = 0; t < 4; ++t) {
                        p0[t] += __shfl_xor_sync(0xffffffff, p0[t], off);
                        p1[t] += __shfl_xor_sync(0xffffffff, p1[t], off);
                    }
                if (g == 0) {
#pragma unroll
                    for (int t = 0; t < 4; ++t) {
                        int col = s * 64 + h * 32 + t * 8 + 2 * tg;
                        aggS[w * 256 + col]     += p0[t];
                        aggS[w * 256 + col + 1] += p1[t];
                    }
                }
            }
        }
    }

    __syncthreads();
    {
        float* aggz = agg + (size_t)blockIdx.z * BB * NN * 256;
        for (int t = tid; t < 512; t += 256) {
            int ni = t >> 8, m = t & 255;
            aggz[((size_t)b * NN + n0 + ni) * 256 + m] =
                aggS[(4 * ni + 0) * 256 + m] + aggS[(4 * ni + 1) * 256 + m] +
                aggS[(4 * ni + 2) * 256 + m] + aggS[(4 * ni + 3) * 256 + m];
        }
    }
}

// =====================================================================
// Output MLP: 16 rows/block, grid 128, double-buffered W with
// CROSS-LAYER prefetch (next layer's slab 0 issued at s==3).
// =====================================================================
#define OT_A0 0
#define OT_A1 12544
#define OT_W  20992
#define OT_TOTAL 121344

__global__ void __launch_bounds__(128, 1)
out_tc_kernel(const float* __restrict__ inputs, const float* __restrict__ agg,
              const unsigned char* __restrict__ wo1, const unsigned char* __restrict__ wo2,
              const unsigned char* __restrict__ wo3,
              const float* __restrict__ bo1, const float* __restrict__ bo2,
              const float* __restrict__ bo3, float* __restrict__ out)
{
    extern __shared__ char smem[];
    const uint32_t sb = smem_u32(smem);
    const int tid = threadIdx.x, lane = tid & 31, w = tid >> 5;
    const int row0 = blockIdx.x * 16;

    const int g = lane >> 2, tg = lane & 3;
    const int arow = lane & 15;
    const uint32_t aoff = (uint32_t)((lane >> 4) << 4);
    const int brow = (lane & 7) + ((lane >> 4) << 3);
    const uint32_t boff = (uint32_t)((lane & 8) << 1);
    const int r0 = g, r1 = g + 8;

    // prefetch Wo1 slab 0 first (overlaps aug build)
    for (int t = tid; t < 3136; t += 128)
        cpa16(sb + OT_W + t * 16, wo1 + (size_t)t * 16);
    CP_COMMIT();

    const float* agg1 = agg + (size_t)BB * NN * 256;
    for (int idx = tid; idx < 16 * 192; idx += 128) {
        int r = idx / 192, pc = idx % 192;
        float2 v;
        if (pc < 64) {
            v = *(const float2*)(inputs + (size_t)(row0 + r) * FF + pc * 2);
        } else {
            size_t o = (size_t)(row0 + r) * 256 + (pc - 64) * 2;
            float2 v0 = *(const float2*)(agg + o);
            float2 v1 = *(const float2*)(agg1 + o);
            v = make_float2(v0.x + v1.x, v0.y + v1.y);
        }
        *(uint32_t*)(smem + OT_A0 + r * 784 + pc * 4) = h2pack(v.x, v.y);
    }
    __syncthreads();

    // ---- layer 1: K=384, N=256 (4 slabs), relu -> A1 ----
#pragma unroll 1
    for (int s = 0; s < 4; ++s) {
        CP_WAIT0();
        __syncthreads();
        if (s < 3) {
            uint32_t wb = OT_W + (uint32_t)(((s + 1) & 1) * 50176);
            for (int t = tid; t < 3136; t += 128)
                cpa16(sb + wb + t * 16, wo1 + (size_t)((s + 1) * 64) * 784 + t * 16);
            CP_COMMIT();
        } else {   // cross-layer: Wo2 slab 0 into buffer 0
            for (int t = tid; t < 2112; t += 128)
                cpa16(sb + OT_W + t * 16, wo2 + (size_t)t * 16);
            CP_COMMIT();
        }
        const uint32_t wbs = sb + OT_W + (uint32_t)((s & 1) * 50176) + (w * 16 + brow) * 784 + boff;
        const uint32_t Ab = sb + OT_A0 + arow * 784 + aoff;
        float c[2][4] = {};
#pragma unroll
        for (int ks = 0; ks < 24; ++ks) {
            uint32_t a[4], bb[4];
            ldm4(Ab + ks * 32, a);
            ldm4(wbs + ks * 32, bb);
            mma_f16(c[0], a, bb[0], bb[1]);
            mma_f16(c[1], a, bb[2], bb[3]);
        }
#pragma unroll
        for (int t = 0; t < 2; ++t) {
            int col = s * 64 + w * 16 + t * 8 + 2 * tg;
            float bc0 = bo1[col], bc1 = bo1[col + 1];
            *(uint32_t*)(smem + OT_A1 + r0 * 528 + col * 2) =
                h2pack(fmaxf(c[t][0] + bc0, 0.f), fmaxf(c[t][1] + bc1, 0.f));
            *(uint32_t*)(smem + OT_A1 + r1 * 528 + col * 2) =
                h2pack(fmaxf(c[t][2] + bc0, 0.f), fmaxf(c[t][3] + bc1, 0.f));
        }
    }

    // ---- layer 2: K=256, N=256 (4 slabs), relu -> A0 (stride 528) ----
#pragma unroll 1
    for (int s = 0; s < 4; ++s) {
        CP_WAIT0();
        __syncthreads();
        if (s < 3) {
            uint32_t wb = OT_W + (uint32_t)(((s + 1) & 1) * 50176);
            for (int t = tid; t < 2112; t += 128)
                cpa16(sb + wb + t * 16, wo2 + (size_t)((s + 1) * 64) * 528 + t * 16);
            CP_COMMIT();
        } else {   // cross-layer: Wo3 slab 0 into buffer 0
            for (int t = tid; t < 2112; t += 128)
                cpa16(sb + OT_W + t * 16, wo3 + (size_t)t * 16);
            CP_COMMIT();
        }
        const uint32_t wbs = sb + OT_W + (uint32_t)((s & 1) * 50176) + (w * 16 + brow) * 528 + boff;
        const uint32_t Ab = sb + OT_A1 + arow * 528 + aoff;
        float c[2][4] = {};
#pragma unroll
        for (int ks = 0; ks < 16; ++ks) {
            uint32_t a[4], bb[4];
            ldm4(Ab + ks * 32, a);
            ldm4(wbs + ks * 32, bb);
            mma_f16(c[0], a, bb[0], bb[1]);
            mma_f16(c[1], a, bb[2], bb[3]);
        }
#pragma unroll
        for (int t = 0; t < 2; ++t) {
            int col = s * 64 + w * 16 + t * 8 + 2 * tg;
            float bc0 = bo2[col], bc1 = bo2[col + 1];
            *(uint32_t*)(smem + OT_A0 + r0 * 528 + col * 2) =
                h2pack(fmaxf(c[t][0] + bc0, 0.f), fmaxf(c[t][1] + bc1, 0.f));
            *(uint32_t*)(smem + OT_A0 + r1 * 528 + col * 2) =
                h2pack(fmaxf(c[t][2] + bc0, 0.f), fmaxf(c[t][3] + bc1, 0.f));
        }
    }

    // ---- layer 3: K=256, N=128 (2 slabs), + residual -> out ----
#pragma unroll 1
    for (int s = 0; s < 2; ++s) {
        CP_WAIT0();
        __syncthreads();
        if (s < 1) {
            uint32_t wb = OT_W + 50176u;
            for (int t = tid; t < 2112; t += 128)
                cpa16(sb + wb + t * 16, wo3 + (size_t)64 * 528 + t * 16);
            CP_COMMIT();
        }
        const uint32_t wbs = sb + OT_W + (uint32_t)((s & 1) * 50176) + (w * 16 + brow) * 528 + boff;
        const uint32_t Ab = sb + OT_A0 + arow * 528 + aoff;
        float c[2][4] = {};
#pragma unroll
        for (int ks = 0; ks < 16; ++ks) {
            uint32_t a[4], bb[4];
            ldm4(Ab + ks * 32, a);
            ldm4(wbs + ks * 32, bb);
            mma_f16(c[0], a, bb[0], bb[1]);
            mma_f16(c[1], a, bb[2], bb[3]);
        }
#pragma unroll
        for (int t = 0; t < 2; ++t) {
            int col = s * 64 + w * 16 + t * 8 + 2 * tg;
            float bc0 = bo3[col], bc1 = bo3[col + 1];
            float2 e0 = *(const float2*)(inputs + (size_t)(row0 + r0) * FF + col);
            float2 e1 = *(const float2*)(inputs + (size_t)(row0 + r1) * FF + col);
            *(float2*)(out + (size_t)(row0 + r0) * FF + col) =
                make_float2(e0.x + c[t][0] + bc0, e0.y + c[t][1] + bc1);
            *(float2*)(out + (size_t)(row0 + r1) * FF + col) =
                make_float2(e1.x + c[t][2] + bc0, e1.y + c[t][3] + bc1);
        }
    }
}

// =====================================================================
extern "C" void kernel_launch(void* const* d_in, const int* in_sizes, int n_in,
                              void* d_out, int out_size)
{
    const float* inputs   = (const float*)d_in[0];
    const float* rel_type = (const float*)d_in[1];
    const float* W1  = (const float*)d_in[4];
    const float* b1  = (const float*)d_in[5];
    const float* W2  = (const float*)d_in[6];
    const float* b2  = (const float*)d_in[7];
    const float* Wo1 = (const float*)d_in[8];
    const float* bo1 = (const float*)d_in[9];
    const float* Wo2 = (const float*)d_in[10];
    const float* bo2 = (const float*)d_in[11];
    const float* Wo3 = (const float*)d_in[12];
    const float* bo3 = (const float*)d_in[13];
    float* out = (float*)d_out;

    float *agg, *hbp;
    uint16_t* simg;
    unsigned char *w1r, *w1s, *w2i, *wo1i, *wo2i, *wo3i;
    cudaGetSymbolAddress((void**)&agg, g_agg);
    cudaGetSymbolAddress((void**)&hbp, g_hb);
    cudaGetSymbolAddress((void**)&simg, g_simg);
    cudaGetSymbolAddress((void**)&w1r, g_w1r);
    cudaGetSymbolAddress((void**)&w1s, g_w1s);
    cudaGetSymbolAddress((void**)&w2i, g_w2img);
    cudaGetSymbolAddress((void**)&wo1i, g_wo1);
    cudaGetSymbolAddress((void**)&wo2i, g_wo2);
    cudaGetSymbolAddress((void**)&wo3i, g_wo3);

    cudaFuncSetAttribute(edge_kernel, cudaFuncAttributeMaxDynamicSharedMemorySize, SE_TOTAL);
    cudaFuncSetAttribute(ns_kernel, cudaFuncAttributeMaxDynamicSharedMemorySize, NS_TOTAL);
    cudaFuncSetAttribute(out_tc_kernel, cudaFuncAttributeMaxDynamicSharedMemorySize, OT_TOTAL);

    prep_all_kernel<<<704, 256>>>(W1, W2, Wo1, Wo2, Wo3,
                                  w1r, w1s, w2i, wo1i, wo2i, wo3i);
    ns_kernel<<<dim3(KK, BB, 4), 256, NS_TOTAL>>>(inputs, w1r, w1s, b1, hbp, simg);
    edge_kernel<<<dim3(NN / 2, BB, 2), 256, SE_TOTAL>>>(rel_type, w2i, simg, hbp, b2, agg);
    out_tc_kernel<<<BB * NN / 16, 128, OT_TOTAL>>>(inputs, agg, wo1i, wo2i, wo3i,
                                                   bo1, bo2, bo3, out);
}

// round 17
// speedup vs baseline: 1.0080x; 1.0080x over previous
#include <cuda_runtime.h>
#include <cuda_bf16.h>
#include <cuda_fp16.h>
#include <cstdint>

#define BB 32
#define NN 64
#define FF 128
#define KK 4
#define EE 4032

// ---------------- static device scratch (no allocations) ----------------
__device__ __align__(16) unsigned char g_w1r[KK * 2 * 256 * 272];
__device__ __align__(16) unsigned char g_w1s[KK * 2 * 256 * 272];
__device__ __align__(16) unsigned char g_w2img[KK * 256 * 528];
__device__ __align__(16) unsigned char g_wo1[256 * 784];
__device__ __align__(16) unsigned char g_wo2[256 * 528];
__device__ __align__(16) unsigned char g_wo3[128 * 528];
__device__ __align__(16) uint32_t g_ximg_hi[BB * NN * 64];
__device__ __align__(16) uint32_t g_ximg_lo[BB * NN * 64];
__device__ __align__(16) float    g_hb[KK * BB * NN * 256];
__device__ __align__(16) uint16_t g_simg[KK * BB * NN * 256];
__device__ float g_agg[2 * BB * NN * 256];   // two k-partials

// ---------------- helpers ----------------
__device__ __forceinline__ uint32_t smem_u32(const void* p) {
    uint32_t a;
    asm("{ .reg .u64 t; cvta.to.shared.u64 t, %1; cvt.u32.u64 %0, t; }" : "=r"(a) : "l"(p));
    return a;
}
__device__ __forceinline__ void split2(float2 v, uint32_t& hi, uint32_t& lo) {  // bf16
    __nv_bfloat162 h2 = __float22bfloat162_rn(v);
    float2 r = make_float2(v.x - __bfloat162float(h2.x), v.y - __bfloat162float(h2.y));
    __nv_bfloat162 l2 = __float22bfloat162_rn(r);
    hi = reinterpret_cast<uint32_t&>(h2);
    lo = reinterpret_cast<uint32_t&>(l2);
}
__device__ __forceinline__ uint32_t h2pack(float a, float b) {
    __half2 h = __float22half2_rn(make_float2(a, b));
    return reinterpret_cast<uint32_t&>(h);
}
__device__ __forceinline__ void ldm4(uint32_t addr, uint32_t r[4]) {
    asm volatile("ldmatrix.sync.aligned.m8n8.x4.shared.b16 {%0,%1,%2,%3}, [%4];"
                 : "=r"(r[0]), "=r"(r[1]), "=r"(r[2]), "=r"(r[3]) : "r"(addr));
}
__device__ __forceinline__ void mma_bf16(float* c, const uint32_t* a, uint32_t b0, uint32_t b1) {
    asm volatile(
        "mma.sync.aligned.m16n8k16.row.col.f32.bf16.bf16.f32 "
        "{%0,%1,%2,%3}, {%4,%5,%6,%7}, {%8,%9}, {%0,%1,%2,%3};"
        : "+f"(c[0]), "+f"(c[1]), "+f"(c[2]), "+f"(c[3])
        : "r"(a[0]), "r"(a[1]), "r"(a[2]), "r"(a[3]), "r"(b0), "r"(b1));
}
__device__ __forceinline__ void mma_f16(float* c, const uint32_t* a, uint32_t b0, uint32_t b1) {
    asm volatile(
        "mma.sync.aligned.m16n8k16.row.col.f32.f16.f16.f32 "
        "{%0,%1,%2,%3}, {%4,%5,%6,%7}, {%8,%9}, {%0,%1,%2,%3};"
        : "+f"(c[0]), "+f"(c[1]), "+f"(c[2]), "+f"(c[3])
        : "r"(a[0]), "r"(a[1]), "r"(a[2]), "r"(a[3]), "r"(b0), "r"(b1));
}
__device__ __forceinline__ void cpa16(uint32_t dst, const void* src) {
    asm volatile("cp.async.cg.shared.global [%0], [%1], 16;" :: "r"(dst), "l"(src));
}
#define CP_COMMIT() asm volatile("cp.async.commit_group;" ::: "memory")
#define CP_WAIT0()  asm volatile("cp.async.wait_group 0;" ::: "memory")
#define CP_WAIT1()  asm volatile("cp.async.wait_group 1;" ::: "memory")

// =====================================================================
// prep_all_kernel: all preps in one launch (R15 configuration).
//  [0,512)      prep_x
//  [512,640)    W1 recv -> g_w1r
//  [640,768)    W1 send -> g_w1s
//  [768,1024)   W2      -> g_w2img
//  [1024,1120)  Wo1     -> g_wo1
//  [1120,1184)  Wo2     -> g_wo2
//  [1184,1216)  Wo3     -> g_wo3
// =====================================================================
__device__ __forceinline__ void prep_w_body(const float* Wk, int koff, int f0, int nn0,
                                            int kt, unsigned char* img, int rstride,
                                            float ts[32][33], int tid)
{
#pragma unroll
    for (int p = 0; p < 4; ++p) {
        int fr = (tid >> 5) + p * 8, nl = tid & 31;
        ts[fr][nl] = Wk[(size_t)(koff + f0 + fr) * 256 + nn0 + nl];
    }
    __syncthreads();
#pragma unroll
    for (int p = 0; p < 2; ++p) {
        int idx = tid + p * 256;
        int nr = idx >> 4, wp = idx & 15;
        uint32_t hi, lo;
        split2(make_float2(ts[2 * wp][nr], ts[2 * wp + 1][nr]), hi, lo);
        size_t rb = (size_t)(nn0 + nr) * rstride + (f0 + 2 * wp) * 2;
        *(uint32_t*)(img + (size_t)(kt * 2 + 0) * 256 * rstride + rb) = hi;
        *(uint32_t*)(img + (size_t)(kt * 2 + 1) * 256 * rstride + rb) = lo;
    }
}
__device__ __forceinline__ void prep_h_body(const float* W, int Ncols, int f0, int nn0,
                                            unsigned char* img, int rstride,
                                            float ts[32][33], int tid)
{
#pragma unroll
    for (int p = 0; p < 4; ++p) {
        int fr = (tid >> 5) + p * 8, nl = tid & 31;
        ts[fr][nl] = W[(size_t)(f0 + fr) * Ncols + nn0 + nl];
    }
    __syncthreads();
#pragma unroll
    for (int p = 0; p < 2; ++p) {
        int idx = tid + p * 256;
        int nr = idx >> 4, wp = idx & 15;
        *(uint32_t*)(img + (size_t)(nn0 + nr) * rstride + (f0 + 2 * wp) * 2) =
            h2pack(ts[2 * wp][nr], ts[2 * wp + 1][nr]);
    }
}

__global__ void __launch_bounds__(256)
prep_all_kernel(const float* __restrict__ inputs,
                const float* __restrict__ W1, const float* __restrict__ W2,
                const float* __restrict__ Wo1, const float* __restrict__ Wo2,
                const float* __restrict__ Wo3,
                uint32_t* __restrict__ xhi, uint32_t* __restrict__ xlo,
                unsigned char* __restrict__ w1r, unsigned char* __restrict__ w1s,
                unsigned char* __restrict__ w2i,
                unsigned char* __restrict__ wo1i, unsigned char* __restrict__ wo2i,
                unsigned char* __restrict__ wo3i)
{
    __shared__ float ts[32][33];
    const int bid = blockIdx.x, tid = threadIdx.x;

    if (bid < 512) {
        int idx = bid * 256 + tid;
        float2 v = ((const float2*)inputs)[idx];
        uint32_t hi, lo;
        split2(v, hi, lo);
        xhi[idx] = hi;
        xlo[idx] = lo;
    } else if (bid < 640) {
        int b2 = bid - 512;
        prep_w_body(W1 + (size_t)(b2 >> 5) * 65536, 0, (b2 & 3) * 32,
                    ((b2 >> 2) & 7) * 32, b2 >> 5, w1r, 272, ts, tid);
    } else if (bid < 768) {
        int b2 = bid - 640;
        prep_w_body(W1 + (size_t)(b2 >> 5) * 65536, 128, (b2 & 3) * 32,
                    ((b2 >> 2) & 7) * 32, b2 >> 5, w1s, 272, ts, tid);
    } else if (bid < 1024) {
        int b3 = bid - 768;
        int f0 = (b3 & 7) * 32, nn0 = ((b3 >> 3) & 7) * 32, kt = b3 >> 6;
        prep_h_body(W2 + (size_t)kt * 65536, 256, f0, nn0,
                    w2i + (size_t)kt * 256 * 528, 528, ts, tid);
    } else if (bid < 1120) {
        int b4 = bid - 1024;
        prep_h_body(Wo1, 256, (b4 % 12) * 32, (b4 / 12) * 32, wo1i, 784, ts, tid);
    } else if (bid < 1184) {
        int b5 = bid - 1120;
        prep_h_body(Wo2, 256, (b5 & 7) * 32, (b5 >> 3) * 32, wo2i, 528, ts, tid);
    } else {
        int b6 = bid - 1184;
        prep_h_body(Wo3, 128, (b6 & 7) * 32, (b6 >> 3) * 32, wo3i, 528, ts, tid);
    }
}

// =====================================================================
// ns_kernel (R15 configuration: reads pre-split X images).
// =====================================================================
#define NS_XHI 0
#define NS_XLO 17408
#define NS_W   34816
#define NS_B1  69632
#define NS_TOTAL 70656

__global__ void __launch_bounds__(256)
ns_kernel(const uint32_t* __restrict__ xhi, const uint32_t* __restrict__ xlo,
          const unsigned char* __restrict__ w1r, const unsigned char* __restrict__ w1s,
          const float* __restrict__ b1, float* __restrict__ hb, uint16_t* __restrict__ simg)
{
    extern __shared__ char smem[];
    const uint32_t sb = smem_u32(smem);
    const int tid = threadIdx.x, lane = tid & 31, w = tid >> 5;
    const int k = blockIdx.x, b = blockIdx.y;
    const int half = blockIdx.z >> 1, s0 = (blockIdx.z & 1) * 2;

    for (int t = tid; t < 1024; t += 256) {
        int row = t >> 4, sgi = t & 15;
        size_t so = (size_t)(b * 64 + row) * 64 + sgi * 4;
        cpa16(sb + NS_XHI + row * 272 + sgi * 16, xhi + so);
        cpa16(sb + NS_XLO + row * 272 + sgi * 16, xlo + so);
    }
    CP_COMMIT();
    if (tid < 64) ((float4*)(smem + NS_B1))[tid] = ((const float4*)(b1 + k * 256))[tid];

    const int g = lane >> 2, tg = lane & 3;
    const int arow = lane & 15;
    const uint32_t aoff = (uint32_t)((lane >> 4) << 4);
    const int brow = (lane & 7) + ((lane >> 4) << 3);
    const uint32_t boff = (uint32_t)((lane & 8) << 1);
    const int wm = w & 3, wn = w >> 2;
    const int m0 = wm * 16;
    const float* b1s = (const float*)(smem + NS_B1);
    const unsigned char* img = half ? w1s : w1r;
    float* outh = hb + ((size_t)k * BB + b) * 64 * 256;
    uint32_t* outs = (uint32_t*)simg + ((size_t)k * BB + b) * 64 * 128;

#pragma unroll 1
    for (int si = 0; si < 2; ++si) {
        int s = s0 + si;
        for (int t = tid; t < 2176; t += 256) {
            int im = t >= 1088;
            uint32_t off = (uint32_t)(t - im * 1088) * 16;
            cpa16(sb + NS_W + (im ? 17408 : 0) + off,
                  img + (size_t)((k * 2 + im) * 256 + s * 64) * 272 + off);
        }
        CP_COMMIT(); CP_WAIT0();
        __syncthreads();
        float c[4][4] = {};
#pragma unroll
        for (int sp = 0; sp < 3; ++sp) {
            uint32_t Ab = sb + (sp == 2 ? NS_XLO : NS_XHI) + (m0 + arow) * 272 + aoff;
            uint32_t Bb = sb + NS_W + (sp == 1 ? 17408u : 0u) + (wn * 32 + brow) * 272 + boff;
#pragma unroll
            for (int ks = 0; ks < 8; ++ks) {
                uint32_t a[4], b0[4], b1f[4];
                ldm4(Ab + ks * 32, a);
                ldm4(Bb + ks * 32, b0);
                ldm4(Bb + 16 * 272 + ks * 32, b1f);
                mma_bf16(c[0], a, b0[0], b0[1]);
                mma_bf16(c[1], a, b0[2], b0[3]);
                mma_bf16(c[2], a, b1f[0], b1f[1]);
                mma_bf16(c[3], a, b1f[2], b1f[3]);
            }
        }
        int r0 = m0 + g, r1 = r0 + 8;
        int cn = s * 64 + wn * 32;
        if (half == 0) {
#pragma unroll
            for (int t = 0; t < 4; ++t) {
                int col = cn + t * 8 + 2 * tg;
                outh[(size_t)r0 * 256 + col]     = c[t][0] + b1s[col];
                outh[(size_t)r0 * 256 + col + 1] = c[t][1] + b1s[col + 1];
                outh[(size_t)r1 * 256 + col]     = c[t][2] + b1s[col];
                outh[(size_t)r1 * 256 + col + 1] = c[t][3] + b1s[col + 1];
            }
        } else {
#pragma unroll
            for (int t = 0; t < 4; ++t) {
                int col = cn + t * 8 + 2 * tg;
                outs[(size_t)r0 * 128 + (col >> 1)] = h2pack(c[t][0], c[t][1]);
                outs[(size_t)r1 * 128 + (col >> 1)] = h2pack(c[t][2], c[t][3]);
            }
        }
        __syncthreads();
    }
}

// ---------------- SMEM map (bytes) for edge kernel ----------------
#define SE_S    0
#define SE_W2   33792
#define SE_HBS  101376
#define SE_B2S  103424
#define SE_RTS  104448
#define SE_AGG  106496
#define SE_TOTAL 114688

// =====================================================================
// Edge kernel (R15 winner, unchanged).
// =====================================================================
__global__ void __launch_bounds__(256, 2)
edge_kernel(const float* __restrict__ rel_type,
            const unsigned char* __restrict__ w2img,
            const uint16_t* __restrict__ simg,
            const float* __restrict__ hb,
            const float* __restrict__ b2,
            float* __restrict__ agg)
{
    extern __shared__ char smem[];
    const uint32_t sb = smem_u32(smem);
    const int tid = threadIdx.x;
    const int lane = tid & 31, w = tid >> 5;
    const int n0 = blockIdx.x * 2, b = blockIdx.y;
    const int kbase = blockIdx.z * 2;

    {
        const unsigned char* sk = (const unsigned char*)simg +
                                  ((size_t)kbase * BB + b) * 64 * 512;
        for (int t = tid; t < 2048; t += 256) {
            int row = t >> 5, ch = t & 31;
            cpa16(sb + SE_S + row * 528 + ch * 16, sk + (size_t)row * 512 + ch * 16);
        }
        for (int t = tid; t < 2112; t += 256)
            cpa16(sb + SE_W2 + t * 16, w2img + (size_t)(kbase * 256) * 528 + t * 16);
        CP_COMMIT();
    }

    if (tid < 128) {
        int node = n0 + (tid >> 6), le = tid & 63;
        float4 v = make_float4(0.f, 0.f, 0.f, 0.f);
        if (le < 63) v = *(const float4*)(rel_type + ((size_t)b * EE + node * 63 + le) * KK);
        *(float4*)(smem + SE_RTS + tid * 16) = v;
    }
    for (int i = tid; i < 2048; i += 256) ((float*)(smem + SE_AGG))[i] = 0.f;

    const int g = lane >> 2, tg = lane & 3;
    const int brow = (lane & 7) + ((lane >> 4) << 3);
    const uint32_t boff = (uint32_t)((lane & 8) << 1);
    const int m0 = w * 16;
    const int nodeg = n0 + (w >> 2);
    const float* rts = (const float*)(smem + SE_RTS);
    const float* b2s = (const float*)(smem + SE_B2S);
    float* aggS = (float*)(smem + SE_AGG);

    const int rw0 = m0 + g, rw1 = rw0 + 8;
    const int le0 = rw0 & 63, le1 = rw1 & 63;
    const float msk0 = (le0 != 63) ? 1.f : 0.f;
    const float msk1 = (le1 != 63) ? 1.f : 0.f;
    const int j0 = (le0 != 63) ? (le0 + (le0 >= nodeg)) : 0;
    const int j1 = (le1 != 63) ? (le1 + (le1 >= nodeg)) : 0;

    uint32_t Ha[64];

#pragma unroll 1
    for (int ki = 0; ki < 2; ++ki) {
        const int k = kbase + ki;
        {
            const float* hbk = hb + (((size_t)k * BB + b) * 64 + n0) * 256;
            if (tid < 128) *(float4*)(smem + SE_HBS + tid * 16) = ((const float4*)hbk)[tid];
            else if (tid < 192)
                ((float4*)(smem + SE_B2S))[tid - 128] = ((const float4*)(b2 + k * 256))[tid - 128];
        }
        if (ki == 0) CP_WAIT0();
        __syncthreads();

        {
            const __half* S0 = (const __half*)(smem + SE_S) + j0 * 264;
            const __half* S1 = (const __half*)(smem + SE_S) + j1 * 264;
            const float* hbs = (const float*)(smem + SE_HBS) + (w >> 2) * 256;
#pragma unroll
            for (int ks = 0; ks < 16; ++ks) {
                int c = ks * 16 + 2 * tg;
                float2 h0 = *(const float2*)(hbs + c);
                float2 h8 = *(const float2*)(hbs + c + 8);
                __half2 a0 = *(const __half2*)(S0 + c);
                __half2 a8 = *(const __half2*)(S0 + c + 8);
                __half2 bq0 = *(const __half2*)(S1 + c);
                __half2 bq8 = *(const __half2*)(S1 + c + 8);
                Ha[ks*4+0] = h2pack(msk0 * fmaxf(h0.x + __low2float(a0), 0.f),
                                    msk0 * fmaxf(h0.y + __high2float(a0), 0.f));
                Ha[ks*4+1] = h2pack(msk1 * fmaxf(h0.x + __low2float(bq0), 0.f),
                                    msk1 * fmaxf(h0.y + __high2float(bq0), 0.f));
                Ha[ks*4+2] = h2pack(msk0 * fmaxf(h8.x + __low2float(a8), 0.f),
                                    msk0 * fmaxf(h8.y + __high2float(a8), 0.f));
                Ha[ks*4+3] = h2pack(msk1 * fmaxf(h8.x + __low2float(bq8), 0.f),
                                    msk1 * fmaxf(h8.y + __high2float(bq8), 0.f));
            }
        }

        const float wr0 = rts[rw0 * 4 + k], wr1 = rts[rw1 * 4 + k];
#pragma unroll 1
        for (int s = 0; s < 4; ++s) {
            const int gs = ki * 4 + s;
            CP_WAIT0();
            __syncthreads();
            if (gs < 7) {
                const int nk = kbase + ((gs + 1) >> 2), nslab = (gs + 1) & 3;
                uint32_t wb = SE_W2 + (uint32_t)(((gs + 1) & 1) * 33792);
                for (int t = tid; t < 2112; t += 256)
                    cpa16(sb + wb + t * 16,
                          w2img + (size_t)(nk * 256 + nslab * 64) * 528 + t * 16);
                if (s == 2 && ki == 0) {
                    const unsigned char* sk = (const unsigned char*)simg +
                                              ((size_t)(k + 1) * BB + b) * 64 * 512;
                    for (int t = tid; t < 2048; t += 256) {
                        int row = t >> 5, ch = t & 31;
                        cpa16(sb + SE_S + row * 528 + ch * 16,
                              sk + (size_t)row * 512 + ch * 16);
                    }
                }
                CP_COMMIT();
            }
            const uint32_t wbase = sb + SE_W2 + (uint32_t)((s & 1) * 33792);
#pragma unroll
            for (int h = 0; h < 2; ++h) {
                const uint32_t wbs = wbase + (h * 32 + brow) * 528 + boff;
                float c[4][4] = {};
#pragma unroll
                for (int ks = 0; ks < 16; ++ks) {
                    uint32_t b0[4], b1f[4];
                    ldm4(wbs + ks * 32, b0);
                    ldm4(wbs + 16 * 528 + ks * 32, b1f);
                    const uint32_t* a = Ha + ks * 4;
                    mma_f16(c[0], a, b0[0], b0[1]);
                    mma_f16(c[1], a, b0[2], b0[3]);
                    mma_f16(c[2], a, b1f[0], b1f[1]);
                    mma_f16(c[3], a, b1f[2], b1f[3]);
                }
                float p0[4], p1[4];
#pragma unroll
                for (int t = 0; t < 4; ++t) {
                    int col = s * 64 + h * 32 + t * 8 + 2 * tg;
                    float bc0 = b2s[col], bc1 = b2s[col + 1];
                    p0[t] = wr0 * fmaxf(c[t][0] + bc0, 0.f) + wr1 * fmaxf(c[t][2] + bc0, 0.f);
                    p1[t] = wr0 * fmaxf(c[t][1] + bc1, 0.f) + wr1 * fmaxf(c[t][3] + bc1, 0.f);
                }
#pragma unroll
                for (int off = 4; off <= 16; off <<= 1)
#pragma unroll
                    for (int t = 0; t < 4; ++t) {
                        p0[t] += __shfl_xor_sync(0xffffffff, p0[t], off);
                        p1[t] += __shfl_xor_sync(0xffffffff, p1[t], off);
                    }
                if (g == 0) {
#pragma unroll
                    for (int t = 0; t < 4; ++t) {
                        int col = s * 64 + h * 32 + t * 8 + 2 * tg;
                        aggS[w * 256 + col]     += p0[t];
                        aggS[w * 256 + col + 1] += p1[t];
                    }
                }
            }
        }
    }

    __syncthreads();
    {
        float* aggz = agg + (size_t)blockIdx.z * BB * NN * 256;
        for (int t = tid; t < 512; t += 256) {
            int ni = t >> 8, m = t & 255;
            aggz[((size_t)b * NN + n0 + ni) * 256 + m] =
                aggS[(4 * ni + 0) * 256 + m] + aggS[(4 * ni + 1) * 256 + m] +
                aggS[(4 * ni + 2) * 256 + m] + aggS[(4 * ni + 3) * 256 + m];
        }
    }
}

// =====================================================================
// Output MLP: 16 rows/block, grid 128, double-buffered W with
// cross-layer prefetch (kept from R16 — measured improvement).
// =====================================================================
#define OT_A0 0
#define OT_A1 12544
#define OT_W  20992
#define OT_TOTAL 121344

__global__ void __launch_bounds__(128, 1)
out_tc_kernel(const float* __restrict__ inputs, const float* __restrict__ agg,
              const unsigned char* __restrict__ wo1, const unsigned char* __restrict__ wo2,
              const unsigned char* __restrict__ wo3,
              const float* __restrict__ bo1, const float* __restrict__ bo2,
              const float* __restrict__ bo3, float* __restrict__ out)
{
    extern __shared__ char smem[];
    const uint32_t sb = smem_u32(smem);
    const int tid = threadIdx.x, lane = tid & 31, w = tid >> 5;
    const int row0 = blockIdx.x * 16;

    const int g = lane >> 2, tg = lane & 3;
    const int arow = lane & 15;
    const uint32_t aoff = (uint32_t)((lane >> 4) << 4);
    const int brow = (lane & 7) + ((lane >> 4) << 3);
    const uint32_t boff = (uint32_t)((lane & 8) << 1);
    const int r0 = g, r1 = g + 8;

    // prefetch Wo1 slab 0 first (overlaps aug build)
    for (int t = tid; t < 3136; t += 128)
        cpa16(sb + OT_W + t * 16, wo1 + (size_t)t * 16);
    CP_COMMIT();

    const float* agg1 = agg + (size_t)BB * NN * 256;
    for (int idx = tid; idx < 16 * 192; idx += 128) {
        int r = idx / 192, pc = idx % 192;
        float2 v;
        if (pc < 64) {
            v = *(const float2*)(inputs + (size_t)(row0 + r) * FF + pc * 2);
        } else {
            size_t o = (size_t)(row0 + r) * 256 + (pc - 64) * 2;
            float2 v0 = *(const float2*)(agg + o);
            float2 v1 = *(const float2*)(agg1 + o);
            v = make_float2(v0.x + v1.x, v0.y + v1.y);
        }
        *(uint32_t*)(smem + OT_A0 + r * 784 + pc * 4) = h2pack(v.x, v.y);
    }
    __syncthreads();

    // ---- layer 1: K=384, N=256 (4 slabs), relu -> A1 ----
#pragma unroll 1
    for (int s = 0; s < 4; ++s) {
        CP_WAIT0();
        __syncthreads();
        if (s < 3) {
            uint32_t wb = OT_W + (uint32_t)(((s + 1) & 1) * 50176);
            for (int t = tid; t < 3136; t += 128)
                cpa16(sb + wb + t * 16, wo1 + (size_t)((s + 1) * 64) * 784 + t * 16);
            CP_COMMIT();
        } else {   // cross-layer: Wo2 slab 0 into buffer 0
            for (int t = tid; t < 2112; t += 128)
                cpa16(sb + OT_W + t * 16, wo2 + (size_t)t * 16);
            CP_COMMIT();
        }
        const uint32_t wbs = sb + OT_W + (uint32_t)((s & 1) * 50176) + (w * 16 + brow) * 784 + boff;
        const uint32_t Ab = sb + OT_A0 + arow * 784 + aoff;
        float c[2][4] = {};
#pragma unroll
        for (int ks = 0; ks < 24; ++ks) {
            uint32_t a[4], bb[4];
            ldm4(Ab + ks * 32, a);
            ldm4(wbs + ks * 32, bb);
            mma_f16(c[0], a, bb[0], bb[1]);
            mma_f16(c[1], a, bb[2], bb[3]);
        }
#pragma unroll
        for (int t = 0; t < 2; ++t) {
            int col = s * 64 + w * 16 + t * 8 + 2 * tg;
            float bc0 = bo1[col], bc1 = bo1[col + 1];
            *(uint32_t*)(smem + OT_A1 + r0 * 528 + col * 2) =
                h2pack(fmaxf(c[t][0] + bc0, 0.f), fmaxf(c[t][1] + bc1, 0.f));
            *(uint32_t*)(smem + OT_A1 + r1 * 528 + col * 2) =
                h2pack(fmaxf(c[t][2] + bc0, 0.f), fmaxf(c[t][3] + bc1, 0.f));
        }
    }

    // ---- layer 2: K=256, N=256 (4 slabs), relu -> A0 (stride 528) ----
#pragma unroll 1
    for (int s = 0; s < 4; ++s) {
        CP_WAIT0();
        __syncthreads();
        if (s < 3) {
            uint32_t wb = OT_W + (uint32_t)(((s + 1) & 1) * 50176);
            for (int t = tid; t < 2112; t += 128)
                cpa16(sb + wb + t * 16, wo2 + (size_t)((s + 1) * 64) * 528 + t * 16);
            CP_COMMIT();
        } else {   // cross-layer: Wo3 slab 0 into buffer 0
            for (int t = tid; t < 2112; t += 128)
                cpa16(sb + OT_W + t * 16, wo3 + (size_t)t * 16);
            CP_COMMIT();
        }
        const uint32_t wbs = sb + OT_W + (uint32_t)((s & 1) * 50176) + (w * 16 + brow) * 528 + boff;
        const uint32_t Ab = sb + OT_A1 + arow * 528 + aoff;
        float c[2][4] = {};
#pragma unroll
        for (int ks = 0; ks < 16; ++ks) {
            uint32_t a[4], bb[4];
            ldm4(Ab + ks * 32, a);
            ldm4(wbs + ks * 32, bb);
            mma_f16(c[0], a, bb[0], bb[1]);
            mma_f16(c[1], a, bb[2], bb[3]);
        }
#pragma unroll
        for (int t = 0; t < 2; ++t) {
            int col = s * 64 + w * 16 + t * 8 + 2 * tg;
            float bc0 = bo2[col], bc1 = bo2[col + 1];
            *(uint32_t*)(smem + OT_A0 + r0 * 528 + col * 2) =
                h2pack(fmaxf(c[t][0] + bc0, 0.f), fmaxf(c[t][1] + bc1, 0.f));
            *(uint32_t*)(smem + OT_A0 + r1 * 528 + col * 2) =
                h2pack(fmaxf(c[t][2] + bc0, 0.f), fmaxf(c[t][3] + bc1, 0.f));
        }
    }

    // ---- layer 3: K=256, N=128 (2 slabs), + residual -> out ----
#pragma unroll 1
    for (int s = 0; s < 2; ++s) {
        CP_WAIT0();
        __syncthreads();
        if (s < 1) {
            uint32_t wb = OT_W + 50176u;
            for (int t = tid; t < 2112; t += 128)
                cpa16(sb + wb + t * 16, wo3 + (size_t)64 * 528 + t * 16);
            CP_COMMIT();
        }
        const uint32_t wbs = sb + OT_W + (uint32_t)((s & 1) * 50176) + (w * 16 + brow) * 528 + boff;
        const uint32_t Ab = sb + OT_A0 + arow * 528 + aoff;
        float c[2][4] = {};
#pragma unroll
        for (int ks = 0; ks < 16; ++ks) {
            uint32_t a[4], bb[4];
            ldm4(Ab + ks * 32, a);
            ldm4(wbs + ks * 32, bb);
            mma_f16(c[0], a, bb[0], bb[1]);
            mma_f16(c[1], a, bb[2], bb[3]);
        }
#pragma unroll
        for (int t = 0; t < 2; ++t) {
            int col = s * 64 + w * 16 + t * 8 + 2 * tg;
            float bc0 = bo3[col], bc1 = bo3[col + 1];
            float2 e0 = *(const float2*)(inputs + (size_t)(row0 + r0) * FF + col);
            float2 e1 = *(const float2*)(inputs + (size_t)(row0 + r1) * FF + col);
            *(float2*)(out + (size_t)(row0 + r0) * FF + col) =
                make_float2(e0.x + c[t][0] + bc0, e0.y + c[t][1] + bc1);
            *(float2*)(out + (size_t)(row0 + r1) * FF + col) =
                make_float2(e1.x + c[t][2] + bc0, e1.y + c[t][3] + bc1);
        }
    }
}

// =====================================================================
extern "C" void kernel_launch(void* const* d_in, const int* in_sizes, int n_in,
                              void* d_out, int out_size)
{
    const float* inputs   = (const float*)d_in[0];
    const float* rel_type = (const float*)d_in[1];
    const float* W1  = (const float*)d_in[4];
    const float* b1  = (const float*)d_in[5];
    const float* W2  = (const float*)d_in[6];
    const float* b2  = (const float*)d_in[7];
    const float* Wo1 = (const float*)d_in[8];
    const float* bo1 = (const float*)d_in[9];
    const float* Wo2 = (const float*)d_in[10];
    const float* bo2 = (const float*)d_in[11];
    const float* Wo3 = (const float*)d_in[12];
    const float* bo3 = (const float*)d_in[13];
    float* out = (float*)d_out;

    float *agg, *hbp;
    uint16_t* simg;
    unsigned char *w1r, *w1s, *w2i, *wo1i, *wo2i, *wo3i;
    uint32_t *xhi, *xlo;
    cudaGetSymbolAddress((void**)&agg, g_agg);
    cudaGetSymbolAddress((void**)&hbp, g_hb);
    cudaGetSymbolAddress((void**)&simg, g_simg);
    cudaGetSymbolAddress((void**)&w1r, g_w1r);
    cudaGetSymbolAddress((void**)&w1s, g_w1s);
    cudaGetSymbolAddress((void**)&w2i, g_w2img);
    cudaGetSymbolAddress((void**)&wo1i, g_wo1);
    cudaGetSymbolAddress((void**)&wo2i, g_wo2);
    cudaGetSymbolAddress((void**)&wo3i, g_wo3);
    cudaGetSymbolAddress((void**)&xhi, g_ximg_hi);
    cudaGetSymbolAddress((void**)&xlo, g_ximg_lo);

    cudaFuncSetAttribute(edge_kernel, cudaFuncAttributeMaxDynamicSharedMemorySize, SE_TOTAL);
    cudaFuncSetAttribute(ns_kernel, cudaFuncAttributeMaxDynamicSharedMemorySize, NS_TOTAL);
    cudaFuncSetAttribute(out_tc_kernel, cudaFuncAttributeMaxDynamicSharedMemorySize, OT_TOTAL);

    prep_all_kernel<<<1216, 256>>>(inputs, W1, W2, Wo1, Wo2, Wo3,
                                   xhi, xlo, w1r, w1s, w2i, wo1i, wo2i, wo3i);
    ns_kernel<<<dim3(KK, BB, 4), 256, NS_TOTAL>>>(xhi, xlo, w1r, w1s, b1, hbp, simg);
    edge_kernel<<<dim3(NN / 2, BB, 2), 256, SE_TOTAL>>>(rel_type, w2i, simg, hbp, b2, agg);
    out_tc_kernel<<<BB * NN / 16, 128, OT_TOTAL>>>(inputs, agg, wo1i, wo2i, wo3i,
                                                   bo1, bo2, bo3, out);
}